// round 3
// baseline (speedup 1.0000x reference)
#include <cuda_runtime.h>
#include <math.h>
#include <limits.h>

#define MAXB 16
#define MAXK 64

// Per-batch accumulators {stc_sum, str_sum, pos_count} + completion ticket.
// Zero at module load; the finalizing block resets them so every launch
// (and every graph replay) starts from zero.
__device__ float g_acc[3 * MAXB];
__device__ unsigned int g_done;

__global__ __launch_bounds__(256) void ainno_loss_kernel(
    const float* __restrict__ ss,
    const float* __restrict__ anchors,
    const float* __restrict__ gt,
    float* __restrict__ out,
    int A, int K, int B, unsigned int nblocks)
{
    const int b = blockIdx.y;
    const int tid = threadIdx.x;

    __shared__ float4 sbox[MAXK];   // gt xyxy
    __shared__ float  sga[MAXK];    // gt area
    __shared__ float  s_acc[3];

    if (tid < 3) s_acc[tid] = 0.0f;
    for (int k = tid; k < K; k += 256) {
        float4 g = *(const float4*)(gt + ((size_t)b * K + k) * 4);
        sbox[k] = make_float4(g.x, g.y, g.x + g.z, g.y + g.w);
        sga[k]  = g.z * g.w;
    }
    __syncthreads();

    // two anchors per thread: a0 = base+tid, a1 = base+tid+256
    const int a0 = blockIdx.x * 512 + tid;

    float ax1[2], ay1[2], ax2[2], ay2[2], aar[2];
    int   key[2];
    bool  valid[2];

#pragma unroll
    for (int i = 0; i < 2; i++) {
        int a = a0 + i * 256;
        valid[i] = (a < A);
        float4 an = valid[i] ? *(const float4*)(anchors + (size_t)a * 4)
                             : make_float4(0.f, 0.f, 0.f, 0.f);
        ax1[i] = an.x;
        ay1[i] = an.y;
        ax2[i] = an.x + an.z;
        ay2[i] = an.y + an.w;
        aar[i] = an.z * an.w;
        key[i] = INT_MIN;
    }

    // argmax(iou) == argmax(inter / (areaA + areaG)) since iou = r/(1-r) is
    // monotone in r. Track (bits(r) with low 6 bits replaced by K-1-k) via
    // integer max: first-max-wins tie-break matches jnp.argmax.
#pragma unroll 4
    for (int k = 0; k < K; k++) {
        float4 gb = sbox[k];
        float gav = sga[k];
        int idbits = (K - 1 - k);
#pragma unroll
        for (int i = 0; i < 2; i++) {
            float lx = fmaxf(ax1[i], gb.x);
            float ly = fmaxf(ay1[i], gb.y);
            float rx = fminf(ax2[i], gb.z);
            float ry = fminf(ay2[i], gb.w);
            float w  = fmaxf(rx - lx, 0.0f);
            float h  = fmaxf(ry - ly, 0.0f);
            float inter = w * h;
            float r = __fdividef(inter, aar[i] + gav);   // r >= 0 always
            int kk = (__float_as_int(r) & ~63) | idbits;
            key[i] = max(key[i], kk);
        }
    }

    float stc = 0.0f, strl = 0.0f, pc = 0.0f;

#pragma unroll
    for (int i = 0; i < 2; i++) {
        if (!valid[i]) continue;
        int a = a0 + i * 256;
        int bidx = (K - 1) - (key[i] & 63);

        // exact iou at the selected target (same formula as the verified
        // round-2 kernel) for the pos/neg thresholds
        float4 gb = sbox[bidx];
        float gav = sga[bidx];
        float lx = fmaxf(ax1[i], gb.x);
        float ly = fmaxf(ay1[i], gb.y);
        float rx = fminf(ax2[i], gb.z);
        float ry = fminf(ay2[i], gb.w);
        float w  = fmaxf(rx - lx, 0.0f);
        float h  = fmaxf(ry - ly, 0.0f);
        float inter = w * h;
        float iou = __fdividef(inter, aar[i] + gav - inter);

        const float* row = ss + ((size_t)b * A + a) * 6;
        const float x = row[4];
        const bool pos = iou >= 0.5f;
        const bool neg = iou < 0.4f;

        if (pos) {
            float emx = expf(-x);
            float p = 1.0f / (1.0f + emx);
            float omp = 1.0f - p;
            stc += 0.25f * log1pf(emx) * omp * omp;
            pc += 1.0f;

            float px = row[0], py = row[1], pw = row[2], ph = row[3];
            float px2 = px + pw, py2 = py + ph;
            float pa = pw * ph;
            float elx = fmaxf(px,  gb.x);
            float ely = fmaxf(py,  gb.y);
            float erx = fminf(px2, gb.z);
            float ery = fminf(py2, gb.w);
            float ew = fmaxf(erx - elx, 0.0f);
            float eh = fmaxf(ery - ely, 0.0f);
            float ei = ew * eh;
            float eiou = ei / (pa + gav - ei);
            strl += -logf(eiou + 0.01f);
        } else if (neg) {
            float emx = expf(-x);
            float p = 1.0f / (1.0f + emx);
            stc += 0.75f * log1pf(expf(x)) * p * p;
        }
    }

    // warp tree reduction
#pragma unroll
    for (int off = 16; off; off >>= 1) {
        stc  += __shfl_xor_sync(0xffffffffu, stc,  off);
        strl += __shfl_xor_sync(0xffffffffu, strl, off);
        pc   += __shfl_xor_sync(0xffffffffu, pc,   off);
    }
    if ((tid & 31) == 0) {
        atomicAdd(&s_acc[0], stc);
        atomicAdd(&s_acc[1], strl);
        atomicAdd(&s_acc[2], pc);
    }
    __syncthreads();

    if (tid == 0) {
        atomicAdd(&g_acc[b * 3 + 0], s_acc[0]);
        atomicAdd(&g_acc[b * 3 + 1], s_acc[1]);
        atomicAdd(&g_acc[b * 3 + 2], s_acc[2]);
        __threadfence();
        unsigned int ticket = atomicAdd(&g_done, 1u);
        if (ticket == nblocks - 1) {
            // all blocks' g_acc contributions are fenced-published
            __threadfence();
            float tot = 0.0f;
            for (int bb = 0; bb < B; bb++) {
                float s0  = atomicAdd(&g_acc[bb * 3 + 0], 0.0f);
                float s1  = atomicAdd(&g_acc[bb * 3 + 1], 0.0f);
                float pcv = atomicAdd(&g_acc[bb * 3 + 2], 0.0f);
                float safe = (pcv > 0.0f) ? pcv : 1.0f;
                tot += s0 / safe;
                tot += (pcv > 0.0f) ? (s1 / pcv) : 0.0f;
            }
            out[0] = tot / (float)B;
            // reset for next launch / graph replay
            for (int j = 0; j < 3 * MAXB; j++) g_acc[j] = 0.0f;
            g_done = 0u;
        }
    }
}

extern "C" void kernel_launch(void* const* d_in, const int* in_sizes, int n_in,
                              void* d_out, int out_size) {
    const float* ss      = (const float*)d_in[0];  // (B, A, 6)
    const float* anchors = (const float*)d_in[1];  // (A, 4)
    const float* gt      = (const float*)d_in[2];  // (B, K, 4)

    const int A = in_sizes[1] / 4;
    const int B = in_sizes[0] / (6 * A);
    const int K = in_sizes[2] / (4 * B);

    float* out = (float*)d_out;

    const int gx = (A + 511) / 512;
    dim3 grid(gx, B);
    ainno_loss_kernel<<<grid, 256>>>(ss, anchors, gt, out, A, K, B,
                                     (unsigned int)(gx * B));
}

// round 4
// speedup vs baseline: 1.0611x; 1.0611x over previous
#include <cuda_runtime.h>
#include <math.h>
#include <limits.h>

#define MAXB 16
#define MAXK 128
#define THREADS 128
#define APT 2                      // anchors per thread
#define ABLK (THREADS * APT)       // anchors per block = 256

// Per-batch accumulators {stc_sum, str_sum, pos_count} + completion ticket.
// Zero at module load; finalizing block resets them each launch/replay.
__device__ float g_acc[3 * MAXB];
__device__ unsigned int g_done;

__global__ __launch_bounds__(THREADS, 12) void ainno_loss_kernel(
    const float* __restrict__ ss,
    const float* __restrict__ anchors,
    const float* __restrict__ gt,
    float* __restrict__ out,
    int A, int K, int B, unsigned int nblocks)
{
    const int b = blockIdx.y;
    const int tid = threadIdx.x;

    // SoA ground-truth tiles for float4 (4-k) loads
    __shared__ __align__(16) float gx1[MAXK], gy1[MAXK], gx2[MAXK], gy2[MAXK], ga[MAXK];
    __shared__ float s_acc[3];

    if (tid < 3) s_acc[tid] = 0.0f;
    for (int k = tid; k < K; k += THREADS) {
        float4 g = *(const float4*)(gt + ((size_t)b * K + k) * 4);
        gx1[k] = g.x;
        gy1[k] = g.y;
        gx2[k] = g.x + g.z;
        gy2[k] = g.y + g.w;
        ga[k]  = g.z * g.w;
    }
    __syncthreads();

    const int a0 = blockIdx.x * ABLK + tid;

    float ax1[APT], ay1[APT], ax2[APT], ay2[APT], aar[APT];
    int   key[APT];
    bool  valid[APT];

#pragma unroll
    for (int i = 0; i < APT; i++) {
        int a = a0 + i * THREADS;
        valid[i] = (a < A);
        float4 an = valid[i] ? *(const float4*)(anchors + (size_t)a * 4)
                             : make_float4(0.f, 0.f, 0.f, 0.f);
        ax1[i] = an.x;
        ay1[i] = an.y;
        ax2[i] = an.x + an.z;
        ay2[i] = an.y + an.w;
        aar[i] = an.z * an.w;
        key[i] = INT_MIN;
    }

    // argmax(iou) == argmax(inter/(areaA+areaG)); key = bits(r) with low 6
    // bits replaced by K-1-k; integer max => first-max-wins like jnp.argmax.
    const float4* vx1 = (const float4*)gx1;
    const float4* vy1 = (const float4*)gy1;
    const float4* vx2 = (const float4*)gx2;
    const float4* vy2 = (const float4*)gy2;
    const float4* vga = (const float4*)ga;

    const int K4 = K >> 2;
#pragma unroll 4
    for (int k4 = 0; k4 < K4; k4++) {
        float4 fx1 = vx1[k4], fy1 = vy1[k4], fx2 = vx2[k4], fy2 = vy2[k4], fga = vga[k4];
        const float* px1 = (const float*)&fx1;
        const float* py1 = (const float*)&fy1;
        const float* px2 = (const float*)&fx2;
        const float* py2 = (const float*)&fy2;
        const float* pga = (const float*)&fga;
#pragma unroll
        for (int j = 0; j < 4; j++) {
            const int idbits = (K - 1) - (k4 * 4 + j);
            const float bx1 = px1[j], by1 = py1[j], bx2 = px2[j], by2 = py2[j], bga = pga[j];
#pragma unroll
            for (int i = 0; i < APT; i++) {
                float lx = fmaxf(ax1[i], bx1);
                float ly = fmaxf(ay1[i], by1);
                float rx = fminf(ax2[i], bx2);
                float ry = fminf(ay2[i], by2);
                float w  = fmaxf(rx - lx, 0.0f);
                float h  = fmaxf(ry - ly, 0.0f);
                float inter = w * h;
                float r = __fdividef(inter, aar[i] + bga);  // r >= 0
                int kk = (__float_as_int(r) & ~63) | idbits;
                key[i] = max(key[i], kk);
            }
        }
    }
    // generic tail (K not multiple of 4) — no-op for K=64
    for (int k = K4 * 4; k < K; k++) {
        const int idbits = (K - 1) - k;
#pragma unroll
        for (int i = 0; i < APT; i++) {
            float lx = fmaxf(ax1[i], gx1[k]);
            float ly = fmaxf(ay1[i], gy1[k]);
            float rx = fminf(ax2[i], gx2[k]);
            float ry = fminf(ay2[i], gy2[k]);
            float w  = fmaxf(rx - lx, 0.0f);
            float h  = fmaxf(ry - ly, 0.0f);
            float inter = w * h;
            float r = __fdividef(inter, aar[i] + ga[k]);
            int kk = (__float_as_int(r) & ~63) | idbits;
            key[i] = max(key[i], kk);
        }
    }

    float stc = 0.0f, strl = 0.0f, pc = 0.0f;

#pragma unroll
    for (int i = 0; i < APT; i++) {
        if (!valid[i]) continue;
        int a = a0 + i * THREADS;
        int bidx = (K - 1) - (key[i] & 63);

        // exact iou at the selected target (same as the verified kernel)
        float gbx1 = gx1[bidx], gby1 = gy1[bidx], gbx2 = gx2[bidx], gby2 = gy2[bidx];
        float gav = ga[bidx];
        float lx = fmaxf(ax1[i], gbx1);
        float ly = fmaxf(ay1[i], gby1);
        float rx = fminf(ax2[i], gbx2);
        float ry = fminf(ay2[i], gby2);
        float w  = fmaxf(rx - lx, 0.0f);
        float h  = fmaxf(ry - ly, 0.0f);
        float inter = w * h;
        float iou = __fdividef(inter, aar[i] + gav - inter);

        const float* row = ss + ((size_t)b * A + a) * 6;
        const float x = row[4];
        const bool pos = iou >= 0.5f;
        const bool neg = iou < 0.4f;

        if (pos) {
            float emx = expf(-x);
            float p = 1.0f / (1.0f + emx);
            float omp = 1.0f - p;
            stc += 0.25f * log1pf(emx) * omp * omp;
            pc += 1.0f;

            float px = row[0], py = row[1], pw = row[2], ph = row[3];
            float px2 = px + pw, py2 = py + ph;
            float pa = pw * ph;
            float elx = fmaxf(px,  gbx1);
            float ely = fmaxf(py,  gby1);
            float erx = fminf(px2, gbx2);
            float ery = fminf(py2, gby2);
            float ew = fmaxf(erx - elx, 0.0f);
            float eh = fmaxf(ery - ely, 0.0f);
            float ei = ew * eh;
            float eiou = ei / (pa + gav - ei);
            strl += -logf(eiou + 0.01f);
        } else if (neg) {
            float emx = expf(-x);
            float p = 1.0f / (1.0f + emx);
            stc += 0.75f * log1pf(expf(x)) * p * p;
        }
    }

    // warp tree reduction
#pragma unroll
    for (int off = 16; off; off >>= 1) {
        stc  += __shfl_xor_sync(0xffffffffu, stc,  off);
        strl += __shfl_xor_sync(0xffffffffu, strl, off);
        pc   += __shfl_xor_sync(0xffffffffu, pc,   off);
    }
    if ((tid & 31) == 0) {
        atomicAdd(&s_acc[0], stc);
        atomicAdd(&s_acc[1], strl);
        atomicAdd(&s_acc[2], pc);
    }
    __syncthreads();

    if (tid == 0) {
        atomicAdd(&g_acc[b * 3 + 0], s_acc[0]);
        atomicAdd(&g_acc[b * 3 + 1], s_acc[1]);
        atomicAdd(&g_acc[b * 3 + 2], s_acc[2]);
        __threadfence();
        unsigned int ticket = atomicAdd(&g_done, 1u);
        if (ticket == nblocks - 1) {
            __threadfence();
            float tot = 0.0f;
            for (int bb = 0; bb < B; bb++) {
                float s0  = atomicAdd(&g_acc[bb * 3 + 0], 0.0f);
                float s1  = atomicAdd(&g_acc[bb * 3 + 1], 0.0f);
                float pcv = atomicAdd(&g_acc[bb * 3 + 2], 0.0f);
                float safe = (pcv > 0.0f) ? pcv : 1.0f;
                tot += s0 / safe;
                tot += (pcv > 0.0f) ? (s1 / pcv) : 0.0f;
            }
            out[0] = tot / (float)B;
            for (int j = 0; j < 3 * MAXB; j++) g_acc[j] = 0.0f;
            g_done = 0u;
        }
    }
}

extern "C" void kernel_launch(void* const* d_in, const int* in_sizes, int n_in,
                              void* d_out, int out_size) {
    const float* ss      = (const float*)d_in[0];  // (B, A, 6)
    const float* anchors = (const float*)d_in[1];  // (A, 4)
    const float* gt      = (const float*)d_in[2];  // (B, K, 4)

    const int A = in_sizes[1] / 4;
    const int B = in_sizes[0] / (6 * A);
    const int K = in_sizes[2] / (4 * B);

    float* out = (float*)d_out;

    const int gx = (A + ABLK - 1) / ABLK;
    dim3 grid(gx, B);
    ainno_loss_kernel<<<grid, THREADS>>>(ss, anchors, gt, out, A, K, B,
                                         (unsigned int)(gx * B));
}